// round 6
// baseline (speedup 1.0000x reference)
#include <cuda_runtime.h>
#include <cuda_bf16.h>
#include <cstdint>

// Problem constants
#define BATCH 2
#define SEQ   2048
#define DMODEL 1024
#define NHEADS 16
#define DHEAD 64
#define TOTDIM 1024          // NHEADS*DHEAD
#define E3 3072              // 3*TOTDIM
#define MTOT (BATCH*SEQ)     // 4096

// ---------------------------------------------------------------------------
// Scratch (static device globals — runtime alloc is forbidden)
// ---------------------------------------------------------------------------
__device__ float g_qkv[(size_t)MTOT * E3];        // [4096,3072] fp32 (attention input)
__device__ __nv_bfloat16 g_xhi[(size_t)MTOT * DMODEL];
__device__ __nv_bfloat16 g_xlo[(size_t)MTOT * DMODEL];
__device__ __nv_bfloat16 g_wqhi[(size_t)E3 * DMODEL];
__device__ __nv_bfloat16 g_wqlo[(size_t)E3 * DMODEL];
__device__ __nv_bfloat16 g_wohi[(size_t)TOTDIM * DMODEL];
__device__ __nv_bfloat16 g_wolo[(size_t)TOTDIM * DMODEL];
__device__ __nv_bfloat16 g_ahi[(size_t)MTOT * TOTDIM];
__device__ __nv_bfloat16 g_alo[(size_t)MTOT * TOTDIM];

// ---------------------------------------------------------------------------
// Portable PTX helpers (no sm_103a-only features)
// ---------------------------------------------------------------------------
__device__ __forceinline__ uint32_t smem_to_u32(const void* p) {
    uint32_t a;
    asm("{ .reg .u64 t; cvta.to.shared.u64 t, %1; cvt.u32.u64 %0, t; }" : "=r"(a) : "l"(p));
    return a;
}

__device__ __forceinline__ void ldmx4(uint32_t* r, uint32_t addr) {
    asm volatile("ldmatrix.sync.aligned.m8n8.x4.shared.b16 {%0,%1,%2,%3}, [%4];"
        : "=r"(r[0]), "=r"(r[1]), "=r"(r[2]), "=r"(r[3]) : "r"(addr));
}

__device__ __forceinline__ void ldmx4t(uint32_t* r, uint32_t addr) {
    asm volatile("ldmatrix.sync.aligned.m8n8.x4.trans.shared.b16 {%0,%1,%2,%3}, [%4];"
        : "=r"(r[0]), "=r"(r[1]), "=r"(r[2]), "=r"(r[3]) : "r"(addr));
}

__device__ __forceinline__ void mma_bf16(float* d, const uint32_t* a, uint32_t b0, uint32_t b1) {
    asm volatile("mma.sync.aligned.m16n8k16.row.col.f32.bf16.bf16.f32 "
        "{%0,%1,%2,%3}, {%4,%5,%6,%7}, {%8,%9}, {%0,%1,%2,%3};"
        : "+f"(d[0]), "+f"(d[1]), "+f"(d[2]), "+f"(d[3])
        : "r"(a[0]), "r"(a[1]), "r"(a[2]), "r"(a[3]), "r"(b0), "r"(b1));
}

__device__ __forceinline__ void cp16(uint32_t dst, const void* src) {
    asm volatile("cp.async.cg.shared.global [%0], [%1], 16;" :: "r"(dst), "l"(src));
}
#define CP_COMMIT() asm volatile("cp.async.commit_group;" ::: "memory")
#define CP_WAIT(n)  asm volatile("cp.async.wait_group %0;" :: "n"(n) : "memory")

// Split two floats into packed bf16x2 hi + bf16x2 lo (residual)
__device__ __forceinline__ void split2(float x, float y, uint32_t& hi, uint32_t& lo) {
    __nv_bfloat16 hx = __float2bfloat16(x), hy = __float2bfloat16(y);
    float rx = x - __bfloat162float(hx), ry = y - __bfloat162float(hy);
    __nv_bfloat16 lx = __float2bfloat16(rx), ly = __float2bfloat16(ry);
    hi = ((uint32_t)*(uint16_t*)&hy << 16) | (uint32_t)*(uint16_t*)&hx;
    lo = ((uint32_t)*(uint16_t*)&ly << 16) | (uint32_t)*(uint16_t*)&lx;
}

#define SWZ(r, off) ((uint32_t)(off) ^ (uint32_t)(((r) & 7) << 4))

// ---------------------------------------------------------------------------
// Split fp32 -> bf16 (hi, lo)
// ---------------------------------------------------------------------------
__global__ void split_bf16(const float* __restrict__ src, __nv_bfloat16* __restrict__ hi,
                           __nv_bfloat16* __restrict__ lo, int n4)
{
    int i = blockIdx.x * blockDim.x + threadIdx.x;
    if (i >= n4) return;
    float4 v = ((const float4*)src)[i];
    float xs[4] = {v.x, v.y, v.z, v.w};
    __nv_bfloat16 h[4], l[4];
#pragma unroll
    for (int k = 0; k < 4; ++k) {
        h[k] = __float2bfloat16(xs[k]);
        l[k] = __float2bfloat16(xs[k] - __bfloat162float(h[k]));
    }
    ((ushort4*)hi)[i] = make_ushort4(((ushort*)h)[0], ((ushort*)h)[1], ((ushort*)h)[2], ((ushort*)h)[3]);
    ((ushort4*)lo)[i] = make_ushort4(((ushort*)l)[0], ((ushort*)l)[1], ((ushort*)l)[2], ((ushort*)l)[3]);
}

// ---------------------------------------------------------------------------
// GEMM: C = Ahi@Bhi^T + Ahi@Blo^T + Alo@Bhi^T ; 2-stage cp.async pipeline.
// A:[M,K], B:[N,K] row-major bf16. CTA tile 256x128, K-chunk 64, 16 warps.
// Stage: Ahi 32K | Alo 32K | Bhi 16K | Blo 16K = 96 KB; 2 stages = 192 KB.
// Warp grid 4m x 4n; warp tile 64x32.
// ---------------------------------------------------------------------------
#define OA_LO 32768
#define OB_HI 65536
#define OB_LO 81920
#define STAGE_BYTES 98304
#define GSMEM (2 * STAGE_BYTES)

__global__ __launch_bounds__(512, 1)
void gemm_mma_bf16x3(const __nv_bfloat16* __restrict__ Ahi, const __nv_bfloat16* __restrict__ Alo,
                     const __nv_bfloat16* __restrict__ Bhi, const __nv_bfloat16* __restrict__ Blo,
                     float* __restrict__ C, int Nn, int K)
{
    extern __shared__ char sm[];
    const uint32_t sbase = smem_to_u32(sm);

    const int tid  = threadIdx.x;
    const int wid  = tid >> 5;
    const int lane = tid & 31;
    const int warp_m = wid & 3;      // 0..3 (64-row slabs)
    const int warp_n = wid >> 2;     // 0..3 (32-col slabs)
    const int row0 = blockIdx.y * 256;
    const int col0 = blockIdx.x * 128;

    const __nv_bfloat16* gAhi = Ahi + (size_t)row0 * K;
    const __nv_bfloat16* gAlo = Alo + (size_t)row0 * K;
    const __nv_bfloat16* gBhi = Bhi + (size_t)col0 * K;
    const __nv_bfloat16* gBlo = Blo + (size_t)col0 * K;

    float acc[4][4][4];
#pragma unroll
    for (int m = 0; m < 4; ++m)
#pragma unroll
        for (int n = 0; n < 4; ++n)
#pragma unroll
            for (int r = 0; r < 4; ++r) acc[m][n][r] = 0.f;

    const int ld_r = lane & 15;
    const int ld_k = (lane >> 4) * 16;

    const int nch = K / 64;

    // Issue async load of chunk c into stage s (512 threads, 12 cp16 each)
    auto issue = [&](int c, int s) {
        const int kc = c * 64;
        const uint32_t st = sbase + (uint32_t)s * STAGE_BYTES;
        // A tiles: 256 rows x 8 uint4 = 2048 per tile -> 4 iters
#pragma unroll
        for (int i = 0; i < 4; ++i) {
            const int idx = i * 512 + tid;
            const int r = idx >> 3;            // 0..255
            const int cb = (idx & 7) * 16;     // byte col
            const uint32_t off = SWZ(r, r * 128 + cb);
            const size_t gofs = (size_t)r * K + kc;
            cp16(st + off,         (const char*)(gAhi + gofs) + cb);
            cp16(st + OA_LO + off, (const char*)(gAlo + gofs) + cb);
        }
        // B tiles: 128 rows x 8 uint4 = 1024 per tile -> 2 iters
#pragma unroll
        for (int i = 0; i < 2; ++i) {
            const int idx = i * 512 + tid;
            const int r = idx >> 3;            // 0..127
            const int cb = (idx & 7) * 16;
            const uint32_t off = SWZ(r, r * 128 + cb);
            const size_t gofs = (size_t)r * K + kc;
            cp16(st + OB_HI + off, (const char*)(gBhi + gofs) + cb);
            cp16(st + OB_LO + off, (const char*)(gBlo + gofs) + cb);
        }
        CP_COMMIT();
    };

    issue(0, 0);

    for (int c = 0; c < nch; ++c) {
        const int s = c & 1;
        if (c + 1 < nch) { issue(c + 1, (c + 1) & 1); CP_WAIT(1); }
        else             { CP_WAIT(0); }
        __syncthreads();

        const uint32_t st = sbase + (uint32_t)s * STAGE_BYTES;
#pragma unroll
        for (int ks = 0; ks < 4; ++ks) {
            uint32_t bhi[2][4], blo[2][4];
#pragma unroll
            for (int nt2 = 0; nt2 < 2; ++nt2) {
                const int r = warp_n * 32 + nt2 * 16 + ld_r;
                uint32_t off = SWZ(r, r * 128 + ks * 32 + ld_k);
                ldmx4(bhi[nt2], st + OB_HI + off);
                ldmx4(blo[nt2], st + OB_LO + off);
            }
#pragma unroll
            for (int mt = 0; mt < 4; ++mt) {
                uint32_t ahi[4], alo[4];
                const int r = warp_m * 64 + mt * 16 + ld_r;
                uint32_t off = SWZ(r, r * 128 + ks * 32 + ld_k);
                ldmx4(ahi, st + off);
                ldmx4(alo, st + OA_LO + off);
#pragma unroll
                for (int nt = 0; nt < 4; ++nt) {
                    const int n2 = nt >> 1, nb = nt & 1;
                    mma_bf16(acc[mt][nt], ahi, bhi[n2][nb], bhi[n2][nb + 2]);
                    mma_bf16(acc[mt][nt], ahi, blo[n2][nb], blo[n2][nb + 2]);
                    mma_bf16(acc[mt][nt], alo, bhi[n2][nb], bhi[n2][nb + 2]);
                }
            }
        }
        __syncthreads();   // stage s consumed; safe for load of chunk c+2
    }

    const int grp = lane >> 2;
    const int qid = (lane & 3) * 2;
#pragma unroll
    for (int mt = 0; mt < 4; ++mt) {
        const int gm = row0 + warp_m * 64 + mt * 16 + grp;
#pragma unroll
        for (int nt = 0; nt < 4; ++nt) {
            const int gn = col0 + warp_n * 32 + nt * 8 + qid;
            *(float2*)(C + (size_t)gm * Nn + gn)       = make_float2(acc[mt][nt][0], acc[mt][nt][1]);
            *(float2*)(C + (size_t)(gm + 8) * Nn + gn) = make_float2(acc[mt][nt][2], acc[mt][nt][3]);
        }
    }
}

// ---------------------------------------------------------------------------
// Tensor-core flash attention (causal), bf16x3 hi/lo, fp32 accum (R4, proven)
// ---------------------------------------------------------------------------
__global__ __launch_bounds__(128)
void attn_mma(const float* __restrict__ qkv,
              __nv_bfloat16* __restrict__ ahi, __nv_bfloat16* __restrict__ alo)
{
    __shared__ char sm[49152];
    const uint32_t sb = smem_to_u32(sm);
    const uint32_t oQh = 0, oQl = 8192, oKh = 16384, oKl = 24576, oVh = 32768, oVl = 40960;

    const int tid = threadIdx.x;
    const int wid = tid >> 5, lane = tid & 31;
    const int grp = lane >> 2, qid = lane & 3;
    const int qt = blockIdx.x, bh = blockIdx.y;
    const int b = bh >> 4, h = bh & 15;
    const int qb = qt * 64;
    const int qr = wid * 16;

    const float* qbase = qkv + (size_t)(b * SEQ) * E3 + h * DHEAD;
    const float* kbase = qbase + TOTDIM;
    const float* vbase = qbase + 2 * TOTDIM;

#pragma unroll
    for (int i = 0; i < 8; ++i) {
        int idx = i * 128 + tid;
        int r = idx >> 4, d0 = (idx & 15) * 4;
        float4 v = *(const float4*)(qbase + (size_t)(qb + r) * E3 + d0);
        v.x *= 0.125f; v.y *= 0.125f; v.z *= 0.125f; v.w *= 0.125f;
        uint32_t h0, l0p, h1, l1p;
        split2(v.x, v.y, h0, l0p);
        split2(v.z, v.w, h1, l1p);
        uint32_t off = SWZ(r, r * 128 + d0 * 2);
        *(uint2*)(sm + oQh + off) = make_uint2(h0, h1);
        *(uint2*)(sm + oQl + off) = make_uint2(l0p, l1p);
    }
    __syncthreads();

    uint32_t aqh[4][4], aql[4][4];
    {
        const int r = qr + (lane & 15);
        const int ch = (lane >> 4) << 4;
#pragma unroll
        for (int ks = 0; ks < 4; ++ks) {
            uint32_t off = SWZ(r, r * 128 + ks * 32 + ch);
            ldmx4(aqh[ks], sb + oQh + off);
            ldmx4(aql[ks], sb + oQl + off);
        }
    }

    float o[8][4];
#pragma unroll
    for (int nd = 0; nd < 8; ++nd)
#pragma unroll
        for (int i = 0; i < 4; ++i) o[nd][i] = 0.f;
    float m0 = -1e30f, m1 = -1e30f, l0 = 0.f, l1 = 0.f;

    for (int jt = 0; jt <= qt; ++jt) {
        const int kb = jt * 64;
        __syncthreads();
#pragma unroll
        for (int i = 0; i < 8; ++i) {
            int idx = i * 128 + tid;
            int r = idx >> 4, d0 = (idx & 15) * 4;
            uint32_t off = SWZ(r, r * 128 + d0 * 2);
            float4 kv = *(const float4*)(kbase + (size_t)(kb + r) * E3 + d0);
            uint32_t h0, l0p, h1, l1p;
            split2(kv.x, kv.y, h0, l0p);
            split2(kv.z, kv.w, h1, l1p);
            *(uint2*)(sm + oKh + off) = make_uint2(h0, h1);
            *(uint2*)(sm + oKl + off) = make_uint2(l0p, l1p);
            float4 vv = *(const float4*)(vbase + (size_t)(kb + r) * E3 + d0);
            split2(vv.x, vv.y, h0, l0p);
            split2(vv.z, vv.w, h1, l1p);
            *(uint2*)(sm + oVh + off) = make_uint2(h0, h1);
            *(uint2*)(sm + oVl + off) = make_uint2(l0p, l1p);
        }
        __syncthreads();

        float s[8][4];
#pragma unroll
        for (int nb = 0; nb < 8; ++nb)
#pragma unroll
            for (int i = 0; i < 4; ++i) s[nb][i] = 0.f;
        {
            const int rB = lane & 15;
            const int chB = (lane >> 4) << 4;
#pragma unroll
            for (int ks = 0; ks < 4; ++ks) {
                uint32_t kh[4][4], kl[4][4];
#pragma unroll
                for (int nt2 = 0; nt2 < 4; ++nt2) {
                    const int r = nt2 * 16 + rB;
                    uint32_t off = SWZ(r, r * 128 + ks * 32 + chB);
                    ldmx4(kh[nt2], sb + oKh + off);
                    ldmx4(kl[nt2], sb + oKl + off);
                }
#pragma unroll
                for (int nt2 = 0; nt2 < 4; ++nt2)
#pragma unroll
                    for (int j = 0; j < 2; ++j) {
                        const int nb = nt2 * 2 + j;
                        mma_bf16(s[nb], aqh[ks], kh[nt2][j], kh[nt2][j + 2]);
                        mma_bf16(s[nb], aqh[ks], kl[nt2][j], kl[nt2][j + 2]);
                        mma_bf16(s[nb], aql[ks], kh[nt2][j], kh[nt2][j + 2]);
                    }
            }
        }

        if (jt == qt) {
            const int row0g = qb + qr + grp;
            const int row1g = row0g + 8;
#pragma unroll
            for (int nb = 0; nb < 8; ++nb) {
                const int c0 = kb + nb * 8 + qid * 2;
                if (c0 > row0g)     s[nb][0] = -1e30f;
                if (c0 + 1 > row0g) s[nb][1] = -1e30f;
                if (c0 > row1g)     s[nb][2] = -1e30f;
                if (c0 + 1 > row1g) s[nb][3] = -1e30f;
            }
        }

        float mx0 = -1e30f, mx1 = -1e30f;
#pragma unroll
        for (int nb = 0; nb < 8; ++nb) {
            mx0 = fmaxf(mx0, fmaxf(s[nb][0], s[nb][1]));
            mx1 = fmaxf(mx1, fmaxf(s[nb][2], s[nb][3]));
        }
        mx0 = fmaxf(mx0, __shfl_xor_sync(0xffffffffu, mx0, 1));
        mx0 = fmaxf(mx0, __shfl_xor_sync(0xffffffffu, mx0, 2));
        mx1 = fmaxf(mx1, __shfl_xor_sync(0xffffffffu, mx1, 1));
        mx1 = fmaxf(mx1, __shfl_xor_sync(0xffffffffu, mx1, 2));
        const float mn0 = fmaxf(m0, mx0), mn1 = fmaxf(m1, mx1);
        const float f0 = __expf(m0 - mn0), f1 = __expf(m1 - mn1);
        m0 = mn0; m1 = mn1;
        float sum0 = 0.f, sum1 = 0.f;
#pragma unroll
        for (int nb = 0; nb < 8; ++nb) {
            s[nb][0] = __expf(s[nb][0] - m0); sum0 += s[nb][0];
            s[nb][1] = __expf(s[nb][1] - m0); sum0 += s[nb][1];
            s[nb][2] = __expf(s[nb][2] - m1); sum1 += s[nb][2];
            s[nb][3] = __expf(s[nb][3] - m1); sum1 += s[nb][3];
        }
        sum0 += __shfl_xor_sync(0xffffffffu, sum0, 1);
        sum0 += __shfl_xor_sync(0xffffffffu, sum0, 2);
        sum1 += __shfl_xor_sync(0xffffffffu, sum1, 1);
        sum1 += __shfl_xor_sync(0xffffffffu, sum1, 2);
        l0 = l0 * f0 + sum0;
        l1 = l1 * f1 + sum1;
#pragma unroll
        for (int nd = 0; nd < 8; ++nd) {
            o[nd][0] *= f0; o[nd][1] *= f0;
            o[nd][2] *= f1; o[nd][3] *= f1;
        }

        uint32_t ph[4][4], pl[4][4];
#pragma unroll
        for (int kp = 0; kp < 4; ++kp) {
            split2(s[2*kp][0],   s[2*kp][1],   ph[kp][0], pl[kp][0]);
            split2(s[2*kp][2],   s[2*kp][3],   ph[kp][1], pl[kp][1]);
            split2(s[2*kp+1][0], s[2*kp+1][1], ph[kp][2], pl[kp][2]);
            split2(s[2*kp+1][2], s[2*kp+1][3], ph[kp][3], pl[kp][3]);
        }

        {
            const int tile = lane >> 3;
            const int ta = tile & 1, ndo = tile >> 1;
            const int rl = lane & 7;
#pragma unroll
            for (int kp = 0; kp < 4; ++kp) {
#pragma unroll
                for (int ndp = 0; ndp < 4; ++ndp) {
                    const int r = kp * 16 + ta * 8 + rl;
                    uint32_t off = SWZ(r, r * 128 + (ndp * 2 + ndo) * 16);
                    uint32_t vh[4], vl[4];
                    ldmx4t(vh, sb + oVh + off);
                    ldmx4t(vl, sb + oVl + off);
                    mma_bf16(o[ndp*2],   ph[kp], vh[0], vh[1]);
                    mma_bf16(o[ndp*2],   ph[kp], vl[0], vl[1]);
                    mma_bf16(o[ndp*2],   pl[kp], vh[0], vh[1]);
                    mma_bf16(o[ndp*2+1], ph[kp], vh[2], vh[3]);
                    mma_bf16(o[ndp*2+1], ph[kp], vl[2], vl[3]);
                    mma_bf16(o[ndp*2+1], pl[kp], vh[2], vh[3]);
                }
            }
        }
    }

    const float inv0 = 1.f / l0, inv1 = 1.f / l1;
    const int row0g = qb + qr + grp;
    const size_t base0 = (size_t)(b * SEQ + row0g) * TOTDIM + h * DHEAD;
    const size_t base1 = base0 + (size_t)8 * TOTDIM;
#pragma unroll
    for (int nd = 0; nd < 8; ++nd) {
        const int col = nd * 8 + qid * 2;
        uint32_t hh, ll;
        split2(o[nd][0] * inv0, o[nd][1] * inv0, hh, ll);
        *(uint32_t*)(ahi + base0 + col) = hh;
        *(uint32_t*)(alo + base0 + col) = ll;
        split2(o[nd][2] * inv1, o[nd][3] * inv1, hh, ll);
        *(uint32_t*)(ahi + base1 + col) = hh;
        *(uint32_t*)(alo + base1 + col) = ll;
    }
}

// ---------------------------------------------------------------------------
extern "C" void kernel_launch(void* const* d_in, const int* in_sizes, int n_in,
                              void* d_out, int out_size)
{
    const float* x    = (const float*)d_in[0];   // [2,2048,1024]
    const float* Wqkv = (const float*)d_in[1];   // [3072,1024]
    const float* Wout = (const float*)d_in[2];   // [1024,1024]
    float* out = (float*)d_out;                  // [2,2048,1024]

    float *qkv;
    __nv_bfloat16 *xhi, *xlo, *wqhi, *wqlo, *wohi, *wolo, *ahi, *alo;
    cudaGetSymbolAddress((void**)&qkv,  g_qkv);
    cudaGetSymbolAddress((void**)&xhi,  g_xhi);
    cudaGetSymbolAddress((void**)&xlo,  g_xlo);
    cudaGetSymbolAddress((void**)&wqhi, g_wqhi);
    cudaGetSymbolAddress((void**)&wqlo, g_wqlo);
    cudaGetSymbolAddress((void**)&wohi, g_wohi);
    cudaGetSymbolAddress((void**)&wolo, g_wolo);
    cudaGetSymbolAddress((void**)&ahi,  g_ahi);
    cudaGetSymbolAddress((void**)&alo,  g_alo);

    cudaFuncSetAttribute(gemm_mma_bf16x3, cudaFuncAttributeMaxDynamicSharedMemorySize, GSMEM);

    // Split inputs to bf16 hi/lo
    {
        int n4 = MTOT * DMODEL / 4;
        split_bf16<<<(n4 + 255) / 256, 256>>>(x, xhi, xlo, n4);
        n4 = E3 * DMODEL / 4;
        split_bf16<<<(n4 + 255) / 256, 256>>>(Wqkv, wqhi, wqlo, n4);
        n4 = TOTDIM * DMODEL / 4;
        split_bf16<<<(n4 + 255) / 256, 256>>>(Wout, wohi, wolo, n4);
    }

    // 1) qkv = x @ Wqkv^T : [4096, 3072]
    gemm_mma_bf16x3<<<dim3(E3/128, MTOT/256), 512, GSMEM>>>(xhi, xlo, wqhi, wqlo, qkv, E3, DMODEL);

    // 2) causal attention -> ahi/alo bf16 [4096, 1024]
    attn_mma<<<dim3(SEQ/64, BATCH*NHEADS), 128>>>(qkv, ahi, alo);

    // 3) out = attn @ Wout^T : [4096, 1024]
    gemm_mma_bf16x3<<<dim3(TOTDIM/128, MTOT/256), 512, GSMEM>>>(ahi, alo, wohi, wolo, out, TOTDIM, DMODEL);
}

// round 7
// speedup vs baseline: 1.1008x; 1.1008x over previous
#include <cuda_runtime.h>
#include <cuda_bf16.h>
#include <cstdint>

// Problem constants
#define BATCH 2
#define SEQ   2048
#define DMODEL 1024
#define NHEADS 16
#define DHEAD 64
#define TOTDIM 1024          // NHEADS*DHEAD
#define E3 3072              // 3*TOTDIM
#define MTOT (BATCH*SEQ)     // 4096

// ---------------------------------------------------------------------------
// Scratch (static device globals — runtime alloc is forbidden)
// ---------------------------------------------------------------------------
__device__ __nv_bfloat16 g_qkvhi[(size_t)MTOT * E3];   // [4096,3072] bf16 hi
__device__ __nv_bfloat16 g_qkvlo[(size_t)MTOT * E3];   // [4096,3072] bf16 lo
__device__ __nv_bfloat16 g_xhi[(size_t)MTOT * DMODEL];
__device__ __nv_bfloat16 g_xlo[(size_t)MTOT * DMODEL];
__device__ __nv_bfloat16 g_wqhi[(size_t)E3 * DMODEL];
__device__ __nv_bfloat16 g_wqlo[(size_t)E3 * DMODEL];
__device__ __nv_bfloat16 g_wohi[(size_t)TOTDIM * DMODEL];
__device__ __nv_bfloat16 g_wolo[(size_t)TOTDIM * DMODEL];
__device__ __nv_bfloat16 g_ahi[(size_t)MTOT * TOTDIM];
__device__ __nv_bfloat16 g_alo[(size_t)MTOT * TOTDIM];

// ---------------------------------------------------------------------------
// Portable PTX helpers (no sm_103a-only features)
// ---------------------------------------------------------------------------
__device__ __forceinline__ uint32_t smem_to_u32(const void* p) {
    uint32_t a;
    asm("{ .reg .u64 t; cvta.to.shared.u64 t, %1; cvt.u32.u64 %0, t; }" : "=r"(a) : "l"(p));
    return a;
}

__device__ __forceinline__ void ldmx4(uint32_t* r, uint32_t addr) {
    asm volatile("ldmatrix.sync.aligned.m8n8.x4.shared.b16 {%0,%1,%2,%3}, [%4];"
        : "=r"(r[0]), "=r"(r[1]), "=r"(r[2]), "=r"(r[3]) : "r"(addr));
}

__device__ __forceinline__ void ldmx4t(uint32_t* r, uint32_t addr) {
    asm volatile("ldmatrix.sync.aligned.m8n8.x4.trans.shared.b16 {%0,%1,%2,%3}, [%4];"
        : "=r"(r[0]), "=r"(r[1]), "=r"(r[2]), "=r"(r[3]) : "r"(addr));
}

__device__ __forceinline__ void mma_bf16(float* d, const uint32_t* a, uint32_t b0, uint32_t b1) {
    asm volatile("mma.sync.aligned.m16n8k16.row.col.f32.bf16.bf16.f32 "
        "{%0,%1,%2,%3}, {%4,%5,%6,%7}, {%8,%9}, {%0,%1,%2,%3};"
        : "+f"(d[0]), "+f"(d[1]), "+f"(d[2]), "+f"(d[3])
        : "r"(a[0]), "r"(a[1]), "r"(a[2]), "r"(a[3]), "r"(b0), "r"(b1));
}

__device__ __forceinline__ void cp16(uint32_t dst, const void* src) {
    asm volatile("cp.async.cg.shared.global [%0], [%1], 16;" :: "r"(dst), "l"(src));
}
#define CP_COMMIT() asm volatile("cp.async.commit_group;" ::: "memory")
#define CP_WAIT(n)  asm volatile("cp.async.wait_group %0;" :: "n"(n) : "memory")

// Split two floats into packed bf16x2 hi + bf16x2 lo (residual)
__device__ __forceinline__ void split2(float x, float y, uint32_t& hi, uint32_t& lo) {
    __nv_bfloat16 hx = __float2bfloat16(x), hy = __float2bfloat16(y);
    float rx = x - __bfloat162float(hx), ry = y - __bfloat162float(hy);
    __nv_bfloat16 lx = __float2bfloat16(rx), ly = __float2bfloat16(ry);
    hi = ((uint32_t)*(uint16_t*)&hy << 16) | (uint32_t)*(uint16_t*)&hx;
    lo = ((uint32_t)*(uint16_t*)&ly << 16) | (uint32_t)*(uint16_t*)&lx;
}

#define SWZ(r, off) ((uint32_t)(off) ^ (uint32_t)(((r) & 7) << 4))

// ---------------------------------------------------------------------------
// Split fp32 -> bf16 (hi, lo)
// ---------------------------------------------------------------------------
__global__ void split_bf16(const float* __restrict__ src, __nv_bfloat16* __restrict__ hi,
                           __nv_bfloat16* __restrict__ lo, int n4)
{
    int i = blockIdx.x * blockDim.x + threadIdx.x;
    if (i >= n4) return;
    float4 v = ((const float4*)src)[i];
    float xs[4] = {v.x, v.y, v.z, v.w};
    __nv_bfloat16 h[4], l[4];
#pragma unroll
    for (int k = 0; k < 4; ++k) {
        h[k] = __float2bfloat16(xs[k]);
        l[k] = __float2bfloat16(xs[k] - __bfloat162float(h[k]));
    }
    ((ushort4*)hi)[i] = make_ushort4(((ushort*)h)[0], ((ushort*)h)[1], ((ushort*)h)[2], ((ushort*)h)[3]);
    ((ushort4*)lo)[i] = make_ushort4(((ushort*)l)[0], ((ushort*)l)[1], ((ushort*)l)[2], ((ushort*)l)[3]);
}

// ---------------------------------------------------------------------------
// GEMM: C = Ahi@Bhi^T + Ahi@Blo^T + Alo@Bhi^T ; 2-stage cp.async pipeline.
// CTA tile 256x128, 16 warps (4m x 4n), warp tile 64x32, K-chunk 64.
// Epilogue: SPLIT_OUT ? write bf16 hi/lo : write fp32.
// ---------------------------------------------------------------------------
#define OA_LO 32768
#define OB_HI 65536
#define OB_LO 81920
#define STAGE_BYTES 98304
#define GSMEM (2 * STAGE_BYTES)

template<bool SPLIT_OUT>
__global__ __launch_bounds__(512, 1)
void gemm_mma_bf16x3(const __nv_bfloat16* __restrict__ Ahi, const __nv_bfloat16* __restrict__ Alo,
                     const __nv_bfloat16* __restrict__ Bhi, const __nv_bfloat16* __restrict__ Blo,
                     float* __restrict__ C, __nv_bfloat16* __restrict__ Chi,
                     __nv_bfloat16* __restrict__ Clo, int Nn, int K)
{
    extern __shared__ char sm[];
    const uint32_t sbase = smem_to_u32(sm);

    const int tid  = threadIdx.x;
    const int wid  = tid >> 5;
    const int lane = tid & 31;
    const int warp_m = wid & 3;
    const int warp_n = wid >> 2;
    const int row0 = blockIdx.y * 256;
    const int col0 = blockIdx.x * 128;

    const __nv_bfloat16* gAhi = Ahi + (size_t)row0 * K;
    const __nv_bfloat16* gAlo = Alo + (size_t)row0 * K;
    const __nv_bfloat16* gBhi = Bhi + (size_t)col0 * K;
    const __nv_bfloat16* gBlo = Blo + (size_t)col0 * K;

    float acc[4][4][4];
#pragma unroll
    for (int m = 0; m < 4; ++m)
#pragma unroll
        for (int n = 0; n < 4; ++n)
#pragma unroll
            for (int r = 0; r < 4; ++r) acc[m][n][r] = 0.f;

    const int ld_r = lane & 15;
    const int ld_k = (lane >> 4) * 16;
    const int nch = K / 64;

    auto issue = [&](int c, int s) {
        const int kc = c * 64;
        const uint32_t st = sbase + (uint32_t)s * STAGE_BYTES;
#pragma unroll
        for (int i = 0; i < 4; ++i) {
            const int idx = i * 512 + tid;
            const int r = idx >> 3;
            const int cb = (idx & 7) * 16;
            const uint32_t off = SWZ(r, r * 128 + cb);
            const size_t gofs = (size_t)r * K + kc;
            cp16(st + off,         (const char*)(gAhi + gofs) + cb);
            cp16(st + OA_LO + off, (const char*)(gAlo + gofs) + cb);
        }
#pragma unroll
        for (int i = 0; i < 2; ++i) {
            const int idx = i * 512 + tid;
            const int r = idx >> 3;
            const int cb = (idx & 7) * 16;
            const uint32_t off = SWZ(r, r * 128 + cb);
            const size_t gofs = (size_t)r * K + kc;
            cp16(st + OB_HI + off, (const char*)(gBhi + gofs) + cb);
            cp16(st + OB_LO + off, (const char*)(gBlo + gofs) + cb);
        }
        CP_COMMIT();
    };

    issue(0, 0);

    for (int c = 0; c < nch; ++c) {
        const int s = c & 1;
        if (c + 1 < nch) { issue(c + 1, (c + 1) & 1); CP_WAIT(1); }
        else             { CP_WAIT(0); }
        __syncthreads();

        const uint32_t st = sbase + (uint32_t)s * STAGE_BYTES;
#pragma unroll
        for (int ks = 0; ks < 4; ++ks) {
            uint32_t bhi[2][4], blo[2][4];
#pragma unroll
            for (int nt2 = 0; nt2 < 2; ++nt2) {
                const int r = warp_n * 32 + nt2 * 16 + ld_r;
                uint32_t off = SWZ(r, r * 128 + ks * 32 + ld_k);
                ldmx4(bhi[nt2], st + OB_HI + off);
                ldmx4(blo[nt2], st + OB_LO + off);
            }
#pragma unroll
            for (int mt = 0; mt < 4; ++mt) {
                uint32_t ahi[4], alo[4];
                const int r = warp_m * 64 + mt * 16 + ld_r;
                uint32_t off = SWZ(r, r * 128 + ks * 32 + ld_k);
                ldmx4(ahi, st + off);
                ldmx4(alo, st + OA_LO + off);
#pragma unroll
                for (int nt = 0; nt < 4; ++nt) {
                    const int n2 = nt >> 1, nb = nt & 1;
                    mma_bf16(acc[mt][nt], ahi, bhi[n2][nb], bhi[n2][nb + 2]);
                    mma_bf16(acc[mt][nt], ahi, blo[n2][nb], blo[n2][nb + 2]);
                    mma_bf16(acc[mt][nt], alo, bhi[n2][nb], bhi[n2][nb + 2]);
                }
            }
        }
        __syncthreads();
    }

    const int grp = lane >> 2;
    const int qid = (lane & 3) * 2;
#pragma unroll
    for (int mt = 0; mt < 4; ++mt) {
        const int gm = row0 + warp_m * 64 + mt * 16 + grp;
#pragma unroll
        for (int nt = 0; nt < 4; ++nt) {
            const int gn = col0 + warp_n * 32 + nt * 8 + qid;
            if (SPLIT_OUT) {
                uint32_t hh, ll;
                split2(acc[mt][nt][0], acc[mt][nt][1], hh, ll);
                *(uint32_t*)(Chi + (size_t)gm * Nn + gn) = hh;
                *(uint32_t*)(Clo + (size_t)gm * Nn + gn) = ll;
                split2(acc[mt][nt][2], acc[mt][nt][3], hh, ll);
                *(uint32_t*)(Chi + (size_t)(gm + 8) * Nn + gn) = hh;
                *(uint32_t*)(Clo + (size_t)(gm + 8) * Nn + gn) = ll;
            } else {
                *(float2*)(C + (size_t)gm * Nn + gn)       = make_float2(acc[mt][nt][0], acc[mt][nt][1]);
                *(float2*)(C + (size_t)(gm + 8) * Nn + gn) = make_float2(acc[mt][nt][2], acc[mt][nt][3]);
            }
        }
    }
}

// ---------------------------------------------------------------------------
// Tensor-core flash attention (causal), pre-split bf16 hi/lo inputs.
// 128 threads = 4 warps; 64-query x 64-key tiles; cp.async 2-stage K/V pipe.
// Smem: Qh 8K | Ql 8K | 2 stages x (Kh|Kl|Vh|Vl = 32K) = 80 KB.
// ---------------------------------------------------------------------------
#define ATT_SMEM 81920
#define AKV(s)  (16384 + (s) * 32768)

__global__ __launch_bounds__(128)
void attn_mma(const __nv_bfloat16* __restrict__ qh, const __nv_bfloat16* __restrict__ ql,
              __nv_bfloat16* __restrict__ ahi, __nv_bfloat16* __restrict__ alo)
{
    extern __shared__ char sm[];
    const uint32_t sb = smem_to_u32(sm);
    const uint32_t oQh = 0, oQl = 8192;

    const int tid = threadIdx.x;
    const int wid = tid >> 5, lane = tid & 31;
    const int grp = lane >> 2, qid = lane & 3;
    const int qt = blockIdx.x, bh = blockIdx.y;
    const int b = bh >> 4, h = bh & 15;
    const int qb = qt * 64;
    const int qr = wid * 16;

    // byte pointers to this (b,h)'s Q/K/V rows in pre-split qkv
    const char* qhb = (const char*)(qh + (size_t)(b * SEQ) * E3 + h * DHEAD);
    const char* qlb = (const char*)(ql + (size_t)(b * SEQ) * E3 + h * DHEAD);
    const char* khb = qhb + TOTDIM * 2;
    const char* klb = qlb + TOTDIM * 2;
    const char* vhb = qhb + 2 * TOTDIM * 2;
    const char* vlb = qlb + 2 * TOTDIM * 2;
    const size_t rstride = (size_t)E3 * 2;   // bytes per token row

    // ---- Load Q hi/lo tiles (direct copies) ----
#pragma unroll
    for (int i = 0; i < 4; ++i) {
        const int idx = i * 128 + tid;          // 0..511
        const int r = idx >> 3;                 // 0..63
        const int c = (idx & 7) * 16;
        const uint32_t off = SWZ(r, r * 128 + c);
        *(uint4*)(sm + oQh + off) = *(const uint4*)(qhb + (size_t)(qb + r) * rstride + c);
        *(uint4*)(sm + oQl + off) = *(const uint4*)(qlb + (size_t)(qb + r) * rstride + c);
    }

    // issue K/V tiles for key-block jt into stage s
    auto issue_kv = [&](int jt, int s) {
        const int kb = jt * 64;
        const uint32_t st = sb + AKV(s);
#pragma unroll
        for (int i = 0; i < 4; ++i) {
            const int idx = i * 128 + tid;
            const int r = idx >> 3;
            const int c = (idx & 7) * 16;
            const uint32_t off = SWZ(r, r * 128 + c);
            const size_t gofs = (size_t)(kb + r) * rstride + c;
            cp16(st + off,         khb + gofs);
            cp16(st + 8192 + off,  klb + gofs);
            cp16(st + 16384 + off, vhb + gofs);
            cp16(st + 24576 + off, vlb + gofs);
        }
        CP_COMMIT();
    };

    issue_kv(0, 0);
    __syncthreads();   // Q tile visible

    // ---- Hoist Q A-fragments ----
    uint32_t aqh[4][4], aql[4][4];
    {
        const int r = qr + (lane & 15);
        const int ch = (lane >> 4) << 4;
#pragma unroll
        for (int ks = 0; ks < 4; ++ks) {
            uint32_t off = SWZ(r, r * 128 + ks * 32 + ch);
            ldmx4(aqh[ks], sb + oQh + off);
            ldmx4(aql[ks], sb + oQl + off);
        }
    }

    float o[8][4];
#pragma unroll
    for (int nd = 0; nd < 8; ++nd)
#pragma unroll
        for (int i = 0; i < 4; ++i) o[nd][i] = 0.f;
    float m0 = -1e30f, m1 = -1e30f, l0 = 0.f, l1 = 0.f;

    for (int jt = 0; jt <= qt; ++jt) {
        const int kb = jt * 64;
        const int s = jt & 1;
        if (jt + 1 <= qt) { issue_kv(jt + 1, (jt + 1) & 1); CP_WAIT(1); }
        else              { CP_WAIT(0); }
        __syncthreads();

        const uint32_t st = sb + AKV(s);

        // ---- S = Q @ K^T (3-pass bf16) ----
        float sacc[8][4];
#pragma unroll
        for (int nb = 0; nb < 8; ++nb)
#pragma unroll
            for (int i = 0; i < 4; ++i) sacc[nb][i] = 0.f;
        {
            const int rB = lane & 15;
            const int chB = (lane >> 4) << 4;
#pragma unroll
            for (int ks = 0; ks < 4; ++ks) {
                uint32_t kh[4][4], kl[4][4];
#pragma unroll
                for (int nt2 = 0; nt2 < 4; ++nt2) {
                    const int r = nt2 * 16 + rB;
                    uint32_t off = SWZ(r, r * 128 + ks * 32 + chB);
                    ldmx4(kh[nt2], st + off);
                    ldmx4(kl[nt2], st + 8192 + off);
                }
#pragma unroll
                for (int nt2 = 0; nt2 < 4; ++nt2)
#pragma unroll
                    for (int j = 0; j < 2; ++j) {
                        const int nb = nt2 * 2 + j;
                        mma_bf16(sacc[nb], aqh[ks], kh[nt2][j], kh[nt2][j + 2]);
                        mma_bf16(sacc[nb], aqh[ks], kl[nt2][j], kl[nt2][j + 2]);
                        mma_bf16(sacc[nb], aql[ks], kh[nt2][j], kh[nt2][j + 2]);
                    }
            }
        }

        // scale by 1/sqrt(Dh) (exact power of two)
#pragma unroll
        for (int nb = 0; nb < 8; ++nb)
#pragma unroll
            for (int i = 0; i < 4; ++i) sacc[nb][i] *= 0.125f;

        // ---- Causal mask (diagonal tile only) ----
        if (jt == qt) {
            const int row0g = qb + qr + grp;
            const int row1g = row0g + 8;
#pragma unroll
            for (int nb = 0; nb < 8; ++nb) {
                const int c0 = kb + nb * 8 + qid * 2;
                if (c0 > row0g)     sacc[nb][0] = -1e30f;
                if (c0 + 1 > row0g) sacc[nb][1] = -1e30f;
                if (c0 > row1g)     sacc[nb][2] = -1e30f;
                if (c0 + 1 > row1g) sacc[nb][3] = -1e30f;
            }
        }

        // ---- Online softmax ----
        float mx0 = -1e30f, mx1 = -1e30f;
#pragma unroll
        for (int nb = 0; nb < 8; ++nb) {
            mx0 = fmaxf(mx0, fmaxf(sacc[nb][0], sacc[nb][1]));
            mx1 = fmaxf(mx1, fmaxf(sacc[nb][2], sacc[nb][3]));
        }
        mx0 = fmaxf(mx0, __shfl_xor_sync(0xffffffffu, mx0, 1));
        mx0 = fmaxf(mx0, __shfl_xor_sync(0xffffffffu, mx0, 2));
        mx1 = fmaxf(mx1, __shfl_xor_sync(0xffffffffu, mx1, 1));
        mx1 = fmaxf(mx1, __shfl_xor_sync(0xffffffffu, mx1, 2));
        const float mn0 = fmaxf(m0, mx0), mn1 = fmaxf(m1, mx1);
        const float f0 = __expf(m0 - mn0), f1 = __expf(m1 - mn1);
        m0 = mn0; m1 = mn1;
        float sum0 = 0.f, sum1 = 0.f;
#pragma unroll
        for (int nb = 0; nb < 8; ++nb) {
            sacc[nb][0] = __expf(sacc[nb][0] - m0); sum0 += sacc[nb][0];
            sacc[nb][1] = __expf(sacc[nb][1] - m0); sum0 += sacc[nb][1];
            sacc[nb][2] = __expf(sacc[nb][2] - m1); sum1 += sacc[nb][2];
            sacc[nb][3] = __expf(sacc[nb][3] - m1); sum1 += sacc[nb][3];
        }
        sum0 += __shfl_xor_sync(0xffffffffu, sum0, 1);
        sum0 += __shfl_xor_sync(0xffffffffu, sum0, 2);
        sum1 += __shfl_xor_sync(0xffffffffu, sum1, 1);
        sum1 += __shfl_xor_sync(0xffffffffu, sum1, 2);
        l0 = l0 * f0 + sum0;
        l1 = l1 * f1 + sum1;
#pragma unroll
        for (int nd = 0; nd < 8; ++nd) {
            o[nd][0] *= f0; o[nd][1] *= f0;
            o[nd][2] *= f1; o[nd][3] *= f1;
        }

        // ---- P fragments (hi/lo) from S accumulators ----
        uint32_t ph[4][4], pl[4][4];
#pragma unroll
        for (int kp = 0; kp < 4; ++kp) {
            split2(sacc[2*kp][0],   sacc[2*kp][1],   ph[kp][0], pl[kp][0]);
            split2(sacc[2*kp][2],   sacc[2*kp][3],   ph[kp][1], pl[kp][1]);
            split2(sacc[2*kp+1][0], sacc[2*kp+1][1], ph[kp][2], pl[kp][2]);
            split2(sacc[2*kp+1][2], sacc[2*kp+1][3], ph[kp][3], pl[kp][3]);
        }

        // ---- O += P @ V (3-pass), V^T B-frags via ldmatrix.trans ----
        {
            const int tile = lane >> 3;
            const int ta = tile & 1, ndo = tile >> 1;
            const int rl = lane & 7;
#pragma unroll
            for (int kp = 0; kp < 4; ++kp) {
#pragma unroll
                for (int ndp = 0; ndp < 4; ++ndp) {
                    const int r = kp * 16 + ta * 8 + rl;
                    uint32_t off = SWZ(r, r * 128 + (ndp * 2 + ndo) * 16);
                    uint32_t vh[4], vl[4];
                    ldmx4t(vh, st + 16384 + off);
                    ldmx4t(vl, st + 24576 + off);
                    mma_bf16(o[ndp*2],   ph[kp], vh[0], vh[1]);
                    mma_bf16(o[ndp*2],   ph[kp], vl[0], vl[1]);
                    mma_bf16(o[ndp*2],   pl[kp], vh[0], vh[1]);
                    mma_bf16(o[ndp*2+1], ph[kp], vh[2], vh[3]);
                    mma_bf16(o[ndp*2+1], ph[kp], vl[2], vl[3]);
                    mma_bf16(o[ndp*2+1], pl[kp], vh[2], vh[3]);
                }
            }
        }
        __syncthreads();   // stage consumed; safe for next issue
    }

    // ---- Epilogue: normalize, split hi/lo, store ----
    const float inv0 = 1.f / l0, inv1 = 1.f / l1;
    const int row0g = qb + qr + grp;
    const size_t base0 = (size_t)(b * SEQ + row0g) * TOTDIM + h * DHEAD;
    const size_t base1 = base0 + (size_t)8 * TOTDIM;
#pragma unroll
    for (int nd = 0; nd < 8; ++nd) {
        const int col = nd * 8 + qid * 2;
        uint32_t hh, ll;
        split2(o[nd][0] * inv0, o[nd][1] * inv0, hh, ll);
        *(uint32_t*)(ahi + base0 + col) = hh;
        *(uint32_t*)(alo + base0 + col) = ll;
        split2(o[nd][2] * inv1, o[nd][3] * inv1, hh, ll);
        *(uint32_t*)(ahi + base1 + col) = hh;
        *(uint32_t*)(alo + base1 + col) = ll;
    }
}

// ---------------------------------------------------------------------------
extern "C" void kernel_launch(void* const* d_in, const int* in_sizes, int n_in,
                              void* d_out, int out_size)
{
    const float* x    = (const float*)d_in[0];   // [2,2048,1024]
    const float* Wqkv = (const float*)d_in[1];   // [3072,1024]
    const float* Wout = (const float*)d_in[2];   // [1024,1024]
    float* out = (float*)d_out;                  // [2,2048,1024]

    __nv_bfloat16 *qkvhi, *qkvlo, *xhi, *xlo, *wqhi, *wqlo, *wohi, *wolo, *ahi, *alo;
    cudaGetSymbolAddress((void**)&qkvhi, g_qkvhi);
    cudaGetSymbolAddress((void**)&qkvlo, g_qkvlo);
    cudaGetSymbolAddress((void**)&xhi,  g_xhi);
    cudaGetSymbolAddress((void**)&xlo,  g_xlo);
    cudaGetSymbolAddress((void**)&wqhi, g_wqhi);
    cudaGetSymbolAddress((void**)&wqlo, g_wqlo);
    cudaGetSymbolAddress((void**)&wohi, g_wohi);
    cudaGetSymbolAddress((void**)&wolo, g_wolo);
    cudaGetSymbolAddress((void**)&ahi,  g_ahi);
    cudaGetSymbolAddress((void**)&alo,  g_alo);

    cudaFuncSetAttribute(gemm_mma_bf16x3<true>,  cudaFuncAttributeMaxDynamicSharedMemorySize, GSMEM);
    cudaFuncSetAttribute(gemm_mma_bf16x3<false>, cudaFuncAttributeMaxDynamicSharedMemorySize, GSMEM);
    cudaFuncSetAttribute(attn_mma, cudaFuncAttributeMaxDynamicSharedMemorySize, ATT_SMEM);

    // Split inputs to bf16 hi/lo
    {
        int n4 = MTOT * DMODEL / 4;
        split_bf16<<<(n4 + 255) / 256, 256>>>(x, xhi, xlo, n4);
        n4 = E3 * DMODEL / 4;
        split_bf16<<<(n4 + 255) / 256, 256>>>(Wqkv, wqhi, wqlo, n4);
        n4 = TOTDIM * DMODEL / 4;
        split_bf16<<<(n4 + 255) / 256, 256>>>(Wout, wohi, wolo, n4);
    }

    // 1) qkv = x @ Wqkv^T : [4096, 3072] -> bf16 hi/lo directly
    gemm_mma_bf16x3<true><<<dim3(E3/128, MTOT/256), 512, GSMEM>>>(
        xhi, xlo, wqhi, wqlo, nullptr, qkvhi, qkvlo, E3, DMODEL);

    // 2) causal attention -> ahi/alo bf16 [4096, 1024]
    attn_mma<<<dim3(SEQ/64, BATCH*NHEADS), 128, ATT_SMEM>>>(qkvhi, qkvlo, ahi, alo);

    // 3) out = attn @ Wout^T : [4096, 1024] -> fp32
    gemm_mma_bf16x3<false><<<dim3(TOTDIM/128, MTOT/256), 512, GSMEM>>>(
        ahi, alo, wohi, wolo, out, nullptr, nullptr, TOTDIM, DMODEL);
}

// round 9
// speedup vs baseline: 2.6747x; 2.4298x over previous
#include <cuda_runtime.h>
#include <cuda_fp16.h>
#include <cstdint>

// Problem constants
#define BATCH 2
#define SEQ   2048
#define DMODEL 1024
#define NHEADS 16
#define DHEAD 64
#define TOTDIM 1024          // NHEADS*DHEAD
#define E3 3072              // 3*TOTDIM
#define MTOT (BATCH*SEQ)     // 4096

// ---------------------------------------------------------------------------
// Scratch (static device globals — runtime alloc is forbidden)
// ---------------------------------------------------------------------------
__device__ __half g_qkvh[(size_t)MTOT * E3];     // [4096,3072] fp16
__device__ __half g_xh[(size_t)MTOT * DMODEL];
__device__ __half g_wqh[(size_t)E3 * DMODEL];
__device__ __half g_woh[(size_t)TOTDIM * DMODEL];
__device__ __half g_ah[(size_t)MTOT * TOTDIM];   // attention output fp16

// ---------------------------------------------------------------------------
// Portable PTX helpers (no sm_103a-only features)
// ---------------------------------------------------------------------------
__device__ __forceinline__ uint32_t smem_to_u32(const void* p) {
    uint32_t a;
    asm("{ .reg .u64 t; cvta.to.shared.u64 t, %1; cvt.u32.u64 %0, t; }" : "=r"(a) : "l"(p));
    return a;
}

__device__ __forceinline__ void ldmx4(uint32_t* r, uint32_t addr) {
    asm volatile("ldmatrix.sync.aligned.m8n8.x4.shared.b16 {%0,%1,%2,%3}, [%4];"
        : "=r"(r[0]), "=r"(r[1]), "=r"(r[2]), "=r"(r[3]) : "r"(addr));
}

__device__ __forceinline__ void ldmx4t(uint32_t* r, uint32_t addr) {
    asm volatile("ldmatrix.sync.aligned.m8n8.x4.trans.shared.b16 {%0,%1,%2,%3}, [%4];"
        : "=r"(r[0]), "=r"(r[1]), "=r"(r[2]), "=r"(r[3]) : "r"(addr));
}

__device__ __forceinline__ void mma_f16(float* d, const uint32_t* a, uint32_t b0, uint32_t b1) {
    asm volatile("mma.sync.aligned.m16n8k16.row.col.f32.f16.f16.f32 "
        "{%0,%1,%2,%3}, {%4,%5,%6,%7}, {%8,%9}, {%0,%1,%2,%3};"
        : "+f"(d[0]), "+f"(d[1]), "+f"(d[2]), "+f"(d[3])
        : "r"(a[0]), "r"(a[1]), "r"(a[2]), "r"(a[3]), "r"(b0), "r"(b1));
}

__device__ __forceinline__ void cp16(uint32_t dst, const void* src) {
    asm volatile("cp.async.cg.shared.global [%0], [%1], 16;" :: "r"(dst), "l"(src));
}
#define CP_COMMIT() asm volatile("cp.async.commit_group;" ::: "memory")
#define CP_WAIT(n)  asm volatile("cp.async.wait_group %0;" :: "n"(n) : "memory")

__device__ __forceinline__ uint32_t pack_h2(float x, float y) {
    __half2 h = __floats2half2_rn(x, y);
    return *(uint32_t*)&h;
}

#define SWZ(r, off) ((uint32_t)(off) ^ (uint32_t)(((r) & 7) << 4))

// ---------------------------------------------------------------------------
// Convert fp32 -> fp16
// ---------------------------------------------------------------------------
__global__ void to_fp16(const float* __restrict__ src, __half* __restrict__ dst, int n4)
{
    int i = blockIdx.x * blockDim.x + threadIdx.x;
    if (i >= n4) return;
    float4 v = ((const float4*)src)[i];
    uint2 o;
    o.x = pack_h2(v.x, v.y);
    o.y = pack_h2(v.z, v.w);
    ((uint2*)dst)[i] = o;
}

// ---------------------------------------------------------------------------
// GEMM: C[M,N] = A[M,K] @ B[N,K]^T, fp16 in, fp32 accum.
// CTA tile 256x128, 16 warps (4m x 4n), warp tile 64x32, K-chunk 64.
// 2-stage cp.async pipeline. Stage: A 32K | B 16K = 48 KB.
// Epilogue: OUT_HALF ? fp16 : fp32.
// ---------------------------------------------------------------------------
#define OB_OFF 32768
#define STAGE_BYTES 49152
#define GSMEM (2 * STAGE_BYTES)

template<bool OUT_HALF>
__global__ __launch_bounds__(512, 1)
void gemm_mma_f16(const __half* __restrict__ A, const __half* __restrict__ B,
                  float* __restrict__ C, __half* __restrict__ Ch, int Nn, int K)
{
    extern __shared__ char sm[];
    const uint32_t sbase = smem_to_u32(sm);

    const int tid  = threadIdx.x;
    const int wid  = tid >> 5;
    const int lane = tid & 31;
    const int warp_m = wid & 3;
    const int warp_n = wid >> 2;
    const int row0 = blockIdx.y * 256;
    const int col0 = blockIdx.x * 128;

    const __half* gA = A + (size_t)row0 * K;
    const __half* gB = B + (size_t)col0 * K;

    float acc[4][4][4];
#pragma unroll
    for (int m = 0; m < 4; ++m)
#pragma unroll
        for (int n = 0; n < 4; ++n)
#pragma unroll
            for (int r = 0; r < 4; ++r) acc[m][n][r] = 0.f;

    const int ld_r = lane & 15;
    const int ld_k = (lane >> 4) * 16;
    const int nch = K / 64;

    auto issue = [&](int c, int s) {
        const int kc = c * 64;
        const uint32_t st = sbase + (uint32_t)s * STAGE_BYTES;
#pragma unroll
        for (int i = 0; i < 4; ++i) {                    // A: 256 rows x 8 uint4
            const int idx = i * 512 + tid;
            const int r = idx >> 3;
            const int cb = (idx & 7) * 16;
            const uint32_t off = SWZ(r, r * 128 + cb);
            cp16(st + off, (const char*)(gA + (size_t)r * K + kc) + cb);
        }
#pragma unroll
        for (int i = 0; i < 2; ++i) {                    // B: 128 rows x 8 uint4
            const int idx = i * 512 + tid;
            const int r = idx >> 3;
            const int cb = (idx & 7) * 16;
            const uint32_t off = SWZ(r, r * 128 + cb);
            cp16(st + OB_OFF + off, (const char*)(gB + (size_t)r * K + kc) + cb);
        }
        CP_COMMIT();
    };

    issue(0, 0);

    for (int c = 0; c < nch; ++c) {
        const int s = c & 1;
        if (c + 1 < nch) { issue(c + 1, (c + 1) & 1); CP_WAIT(1); }
        else             { CP_WAIT(0); }
        __syncthreads();

        const uint32_t st = sbase + (uint32_t)s * STAGE_BYTES;
#pragma unroll
        for (int ks = 0; ks < 4; ++ks) {
            uint32_t bf[2][4];
#pragma unroll
            for (int nt2 = 0; nt2 < 2; ++nt2) {
                const int r = warp_n * 32 + nt2 * 16 + ld_r;
                uint32_t off = SWZ(r, r * 128 + ks * 32 + ld_k);
                ldmx4(bf[nt2], st + OB_OFF + off);
            }
#pragma unroll
            for (int mt = 0; mt < 4; ++mt) {
                uint32_t af[4];
                const int r = warp_m * 64 + mt * 16 + ld_r;
                uint32_t off = SWZ(r, r * 128 + ks * 32 + ld_k);
                ldmx4(af, st + off);
#pragma unroll
                for (int nt = 0; nt < 4; ++nt) {
                    const int n2 = nt >> 1, nb = nt & 1;
                    mma_f16(acc[mt][nt], af, bf[n2][nb], bf[n2][nb + 2]);
                }
            }
        }
        __syncthreads();
    }

    const int grp = lane >> 2;
    const int qid = (lane & 3) * 2;
#pragma unroll
    for (int mt = 0; mt < 4; ++mt) {
        const int gm = row0 + warp_m * 64 + mt * 16 + grp;
#pragma unroll
        for (int nt = 0; nt < 4; ++nt) {
            const int gn = col0 + warp_n * 32 + nt * 8 + qid;
            if (OUT_HALF) {
                *(uint32_t*)(Ch + (size_t)gm * Nn + gn)       = pack_h2(acc[mt][nt][0], acc[mt][nt][1]);
                *(uint32_t*)(Ch + (size_t)(gm + 8) * Nn + gn) = pack_h2(acc[mt][nt][2], acc[mt][nt][3]);
            } else {
                *(float2*)(C + (size_t)gm * Nn + gn)       = make_float2(acc[mt][nt][0], acc[mt][nt][1]);
                *(float2*)(C + (size_t)(gm + 8) * Nn + gn) = make_float2(acc[mt][nt][2], acc[mt][nt][3]);
            }
        }
    }
}

// ---------------------------------------------------------------------------
// Tensor-core flash attention (causal), fp16 single-pass, fp32 accum.
// 128 threads = 4 warps; 64-query x 64-key tiles; cp.async 2-stage K/V pipe.
// Smem: Q 8K | 2 stages x (K 8K | V 8K) = 40 KB.
// ---------------------------------------------------------------------------
#define ATT_SMEM 40960
#define AKV(s)  (8192 + (s) * 16384)

__global__ __launch_bounds__(128)
void attn_mma(const __half* __restrict__ qkv, __half* __restrict__ ao)
{
    extern __shared__ char sm[];
    const uint32_t sb = smem_to_u32(sm);

    const int tid = threadIdx.x;
    const int wid = tid >> 5, lane = tid & 31;
    const int grp = lane >> 2, qid = lane & 3;
    const int qt = blockIdx.x, bh = blockIdx.y;
    const int b = bh >> 4, h = bh & 15;
    const int qb = qt * 64;
    const int qr = wid * 16;

    const char* qpb = (const char*)(qkv + (size_t)(b * SEQ) * E3 + h * DHEAD);
    const char* kpb = qpb + TOTDIM * 2;
    const char* vpb = qpb + 2 * TOTDIM * 2;
    const size_t rstride = (size_t)E3 * 2;   // bytes per token row

    // ---- Load Q tile ----
#pragma unroll
    for (int i = 0; i < 4; ++i) {
        const int idx = i * 128 + tid;          // 0..511
        const int r = idx >> 3;                 // 0..63
        const int c = (idx & 7) * 16;
        const uint32_t off = SWZ(r, r * 128 + c);
        *(uint4*)(sm + off) = *(const uint4*)(qpb + (size_t)(qb + r) * rstride + c);
    }

    auto issue_kv = [&](int jt, int s) {
        const int kb = jt * 64;
        const uint32_t st = sb + AKV(s);
#pragma unroll
        for (int i = 0; i < 4; ++i) {
            const int idx = i * 128 + tid;
            const int r = idx >> 3;
            const int c = (idx & 7) * 16;
            const uint32_t off = SWZ(r, r * 128 + c);
            const size_t gofs = (size_t)(kb + r) * rstride + c;
            cp16(st + off,        kpb + gofs);
            cp16(st + 8192 + off, vpb + gofs);
        }
        CP_COMMIT();
    };

    issue_kv(0, 0);
    __syncthreads();   // Q visible

    // ---- Hoist Q A-fragments ----
    uint32_t aq[4][4];
    {
        const int r = qr + (lane & 15);
        const int ch = (lane >> 4) << 4;
#pragma unroll
        for (int ks = 0; ks < 4; ++ks) {
            uint32_t off = SWZ(r, r * 128 + ks * 32 + ch);
            ldmx4(aq[ks], sb + off);
        }
    }

    float o[8][4];
#pragma unroll
    for (int nd = 0; nd < 8; ++nd)
#pragma unroll
        for (int i = 0; i < 4; ++i) o[nd][i] = 0.f;
    float m0 = -1e30f, m1 = -1e30f, l0 = 0.f, l1 = 0.f;

    for (int jt = 0; jt <= qt; ++jt) {
        const int kb = jt * 64;
        const int s = jt & 1;
        if (jt + 1 <= qt) { issue_kv(jt + 1, (jt + 1) & 1); CP_WAIT(1); }
        else              { CP_WAIT(0); }
        __syncthreads();

        const uint32_t st = sb + AKV(s);

        // ---- S = Q @ K^T ----
        float sacc[8][4];
#pragma unroll
        for (int nb = 0; nb < 8; ++nb)
#pragma unroll
            for (int i = 0; i < 4; ++i) sacc[nb][i] = 0.f;
        {
            const int rB = lane & 15;
            const int chB = (lane >> 4) << 4;
#pragma unroll
            for (int ks = 0; ks < 4; ++ks) {
                uint32_t kf[4][4];
#pragma unroll
                for (int nt2 = 0; nt2 < 4; ++nt2) {
                    const int r = nt2 * 16 + rB;
                    uint32_t off = SWZ(r, r * 128 + ks * 32 + chB);
                    ldmx4(kf[nt2], st + off);
                }
#pragma unroll
                for (int nt2 = 0; nt2 < 4; ++nt2)
#pragma unroll
                    for (int j = 0; j < 2; ++j)
                        mma_f16(sacc[nt2 * 2 + j], aq[ks], kf[nt2][j], kf[nt2][j + 2]);
            }
        }

        // scale by 1/sqrt(Dh)
#pragma unroll
        for (int nb = 0; nb < 8; ++nb)
#pragma unroll
            for (int i = 0; i < 4; ++i) sacc[nb][i] *= 0.125f;

        // ---- Causal mask (diagonal tile only) ----
        if (jt == qt) {
            const int row0g = qb + qr + grp;
            const int row1g = row0g + 8;
#pragma unroll
            for (int nb = 0; nb < 8; ++nb) {
                const int c0 = kb + nb * 8 + qid * 2;
                if (c0 > row0g)     sacc[nb][0] = -1e30f;
                if (c0 + 1 > row0g) sacc[nb][1] = -1e30f;
                if (c0 > row1g)     sacc[nb][2] = -1e30f;
                if (c0 + 1 > row1g) sacc[nb][3] = -1e30f;
            }
        }

        // ---- Online softmax ----
        float mx0 = -1e30f, mx1 = -1e30f;
#pragma unroll
        for (int nb = 0; nb < 8; ++nb) {
            mx0 = fmaxf(mx0, fmaxf(sacc[nb][0], sacc[nb][1]));
            mx1 = fmaxf(mx1, fmaxf(sacc[nb][2], sacc[nb][3]));
        }
        mx0 = fmaxf(mx0, __shfl_xor_sync(0xffffffffu, mx0, 1));
        mx0 = fmaxf(mx0, __shfl_xor_sync(0xffffffffu, mx0, 2));
        mx1 = fmaxf(mx1, __shfl_xor_sync(0xffffffffu, mx1, 1));
        mx1 = fmaxf(mx1, __shfl_xor_sync(0xffffffffu, mx1, 2));
        const float mn0 = fmaxf(m0, mx0), mn1 = fmaxf(m1, mx1);
        const float f0 = __expf(m0 - mn0), f1 = __expf(m1 - mn1);
        m0 = mn0; m1 = mn1;
        float sum0 = 0.f, sum1 = 0.f;
#pragma unroll
        for (int nb = 0; nb < 8; ++nb) {
            sacc[nb][0] = __expf(sacc[nb][0] - m0); sum0 += sacc[nb][0];
            sacc[nb][1] = __expf(sacc[nb][1] - m0); sum0 += sacc[nb][1];
            sacc[nb][2] = __expf(sacc[nb][2] - m1); sum1 += sacc[nb][2];
            sacc[nb][3] = __expf(sacc[nb][3] - m1); sum1 += sacc[nb][3];
        }
        sum0 += __shfl_xor_sync(0xffffffffu, sum0, 1);
        sum0 += __shfl_xor_sync(0xffffffffu, sum0, 2);
        sum1 += __shfl_xor_sync(0xffffffffu, sum1, 1);
        sum1 += __shfl_xor_sync(0xffffffffu, sum1, 2);
        l0 = l0 * f0 + sum0;
        l1 = l1 * f1 + sum1;
#pragma unroll
        for (int nd = 0; nd < 8; ++nd) {
            o[nd][0] *= f0; o[nd][1] *= f0;
            o[nd][2] *= f1; o[nd][3] *= f1;
        }

        // ---- P fragments (fp16) from S accumulators ----
        uint32_t pf[4][4];
#pragma unroll
        for (int kp = 0; kp < 4; ++kp) {
            pf[kp][0] = pack_h2(sacc[2*kp][0],   sacc[2*kp][1]);
            pf[kp][1] = pack_h2(sacc[2*kp][2],   sacc[2*kp][3]);
            pf[kp][2] = pack_h2(sacc[2*kp+1][0], sacc[2*kp+1][1]);
            pf[kp][3] = pack_h2(sacc[2*kp+1][2], sacc[2*kp+1][3]);
        }

        // ---- O += P @ V ; V^T B-frags via ldmatrix.trans ----
        {
            const int tile = lane >> 3;
            const int ta = tile & 1, ndo = tile >> 1;
            const int rl = lane & 7;
#pragma unroll
            for (int kp = 0; kp < 4; ++kp) {
#pragma unroll
                for (int ndp = 0; ndp < 4; ++ndp) {
                    const int r = kp * 16 + ta * 8 + rl;
                    uint32_t off = SWZ(r, r * 128 + (ndp * 2 + ndo) * 16);
                    uint32_t vf[4];
                    ldmx4t(vf, st + 8192 + off);
                    mma_f16(o[ndp*2],   pf[kp], vf[0], vf[1]);
                    mma_f16(o[ndp*2+1], pf[kp], vf[2], vf[3]);
                }
            }
        }
        __syncthreads();   // stage consumed
    }

    // ---- Epilogue: normalize, store fp16 ----
    const float inv0 = 1.f / l0, inv1 = 1.f / l1;
    const int row0g = qb + qr + grp;
    const size_t base0 = (size_t)(b * SEQ + row0g) * TOTDIM + h * DHEAD;
    const size_t base1 = base0 + (size_t)8 * TOTDIM;
#pragma unroll
    for (int nd = 0; nd < 8; ++nd) {
        const int col = nd * 8 + qid * 2;
        *(uint32_t*)(ao + base0 + col) = pack_h2(o[nd][0] * inv0, o[nd][1] * inv0);
        *(uint32_t*)(ao + base1 + col) = pack_h2(o[nd][2] * inv1, o[nd][3] * inv1);
    }
}

// ---------------------------------------------------------------------------
extern "C" void kernel_launch(void* const* d_in, const int* in_sizes, int n_in,
                              void* d_out, int out_size)
{
    const float* x    = (const float*)d_in[0];   // [2,2048,1024]
    const float* Wqkv = (const float*)d_in[1];   // [3072,1024]
    const float* Wout = (const float*)d_in[2];   // [1024,1024]
    float* out = (float*)d_out;                  // [2,2048,1024]

    __half *qkvh, *xh, *wqh, *woh, *ah;
    cudaGetSymbolAddress((void**)&qkvh, g_qkvh);
    cudaGetSymbolAddress((void**)&xh,  g_xh);
    cudaGetSymbolAddress((void**)&wqh, g_wqh);
    cudaGetSymbolAddress((void**)&woh, g_woh);
    cudaGetSymbolAddress((void**)&ah,  g_ah);

    cudaFuncSetAttribute(gemm_mma_f16<true>,  cudaFuncAttributeMaxDynamicSharedMemorySize, GSMEM);
    cudaFuncSetAttribute(gemm_mma_f16<false>, cudaFuncAttributeMaxDynamicSharedMemorySize, GSMEM);
    cudaFuncSetAttribute(attn_mma, cudaFuncAttributeMaxDynamicSharedMemorySize, ATT_SMEM);

    // Convert inputs to fp16
    {
        int n4 = MTOT * DMODEL / 4;
        to_fp16<<<(n4 + 255) / 256, 256>>>(x, xh, n4);
        n4 = E3 * DMODEL / 4;
        to_fp16<<<(n4 + 255) / 256, 256>>>(Wqkv, wqh, n4);
        n4 = TOTDIM * DMODEL / 4;
        to_fp16<<<(n4 + 255) / 256, 256>>>(Wout, woh, n4);
    }

    // 1) qkv = x @ Wqkv^T : [4096, 3072] -> fp16
    gemm_mma_f16<true><<<dim3(E3/128, MTOT/256), 512, GSMEM>>>(
        xh, wqh, nullptr, qkvh, E3, DMODEL);

    // 2) causal attention -> fp16 [4096, 1024]
    attn_mma<<<dim3(SEQ/64, BATCH*NHEADS), 128, ATT_SMEM>>>(qkvh, ah);

    // 3) out = attn @ Wout^T : [4096, 1024] -> fp32
    gemm_mma_f16<false><<<dim3(TOTDIM/128, MTOT/256), 512, GSMEM>>>(
        ah, woh, out, nullptr, TOTDIM, DMODEL);
}